// round 9
// baseline (speedup 1.0000x reference)
#include <cuda_runtime.h>
#include <cuda_bf16.h>
#include <math.h>

#define D_IN  128
#define D_OUT 128
#define KK    64
#define BT    8      // batch rows per block in main kernel

// Scratch (allocation-free rule: __device__ globals)
__device__ float g_D[D_OUT * D_IN * KK];          // PCHIP slopes, layout [o][i][k] (4MB)
__device__ float g_CD[D_IN * KK * 2 * D_OUT];     // transposed [i][k][{ct,dt}][o] (8MB)

// ---------------------------------------------------------------------------
// Kernel 1: PCHIP slopes. One warp per (o,i) row of 64 knots.
// Replicates the reference _pchip_slopes numerics (fp32, EPS=1e-12).
// ---------------------------------------------------------------------------
__global__ void __launch_bounds__(256) slopes_kernel(const float* __restrict__ coeffs) {
    __shared__ float sy[8][KK];
    __shared__ float sd[8][KK];
    const int warp = threadIdx.x >> 5;
    const int lane = threadIdx.x & 31;
    const int pair = blockIdx.x * 8 + warp;   // 0..16383
    const int o = pair >> 7;
    const int i = pair & 127;

    const float hk   = 1.0f / 63.0f;
    const float EPSf = 1e-12f;

    const float* y = coeffs + (o * D_IN + i) * KK;
    sy[warp][lane]      = y[lane];
    sy[warp][lane + 32] = y[lane + 32];
    __syncwarp();

    // deltas: k = 0..62
    sd[warp][lane] = (sy[warp][lane + 1] - sy[warp][lane]) / (hk + EPSf);
    if (lane < 31)
        sd[warp][lane + 32] = (sy[warp][lane + 33] - sy[warp][lane + 32]) / (hk + EPSf);
    __syncwarp();

    float* dst = g_D + (o * D_IN + i) * KK;
    #pragma unroll
    for (int kk = 0; kk < 2; kk++) {
        const int k = lane + kk * 32;
        float dk;
        if (k == 0) {
            float de = sd[warp][0];
            float di = (3.0f * hk * sd[warp][0] - hk * sd[warp][1]) / (2.0f * hk + EPSf);
            if (di * de <= 0.0f) di = 0.0f;
            if (fabsf(di) > 3.0f * fabsf(de)) di = 3.0f * de;
            dk = di;
        } else if (k == 63) {
            float de = sd[warp][62];
            float di = (3.0f * hk * sd[warp][62] - hk * sd[warp][61]) / (2.0f * hk + EPSf);
            if (di * de <= 0.0f) di = 0.0f;
            if (fabsf(di) > 3.0f * fabsf(de)) di = 3.0f * de;
            dk = di;
        } else {
            float d0 = sd[warp][k - 1], d1 = sd[warp][k];
            dk = 0.0f;
            if (d0 * d1 > 0.0f) {
                float w1 = 3.0f * hk, w2 = 3.0f * hk;
                float denom = w1 / (d0 + EPSf) + w2 / (d1 + EPSf);
                dk = (w1 + w2) / (denom + EPSf);
            }
        }
        dst[k] = dk;
    }
}

// ---------------------------------------------------------------------------
// Kernel 2: transpose coeffs + slopes into [i][k][{ct,dt}][o].
// smem-tiled so both reads (over k) and writes (over o) are coalesced.
// Grid: (128 i, 4 o-tiles), 256 threads.
// ---------------------------------------------------------------------------
__global__ void __launch_bounds__(256) transpose_kernel(const float* __restrict__ coeffs) {
    __shared__ float tc[32][KK + 1];
    __shared__ float td[32][KK + 1];
    const int i  = blockIdx.x;
    const int o0 = blockIdx.y * 32;
    const int t  = threadIdx.x;

    const int kl = t & 63;
    const int ob = t >> 6;   // 0..3
    #pragma unroll
    for (int oo = 0; oo < 8; oo++) {
        const int ol = ob + oo * 4;
        const int o  = o0 + ol;
        const int src = (o * D_IN + i) * KK + kl;
        tc[ol][kl] = coeffs[src];
        td[ol][kl] = g_D[src];
    }
    __syncthreads();

    const int ol2 = t & 31;
    const int kb  = t >> 5;  // 0..7
    #pragma unroll
    for (int kk2 = 0; kk2 < 8; kk2++) {
        const int k = kb * 8 + kk2;
        float* dst = g_CD + (size_t)((i * KK + k) * 2) * D_OUT + o0 + ol2;
        dst[0]     = tc[ol2][k];
        dst[D_OUT] = td[ol2][k];
    }
}

// ---------------------------------------------------------------------------
// Kernel 3: main evaluation.
// 128 threads (one per o), BT batch rows per block, accumulated concurrently
// for MLP. Weights (idx + 4 hermite/extrapolation scalars) staged in smem,
// broadcast-read. Extrapolated entries (x<0 / x>1, ~66% of all (b,i)) skip
// the zero-weight coefficient pair -> 33% gather-traffic reduction.
// ---------------------------------------------------------------------------
__global__ void __launch_bounds__(128) kan_main(const float* __restrict__ x,
                                                const float* __restrict__ bias,
                                                float* __restrict__ out, int B) {
    __shared__ int    s_idx[BT][D_IN];
    __shared__ float4 s_w[BT][D_IN];

    const int o  = threadIdx.x;
    const int b0 = blockIdx.x * BT;
    const float hk = 1.0f / 63.0f;

    // Phase 1: per-(b,i) weights (thread o computes i == o's weights for each row)
    #pragma unroll
    for (int r = 0; r < BT; r++) {
        const float xv = x[(b0 + r) * D_IN + o];
        float xc = fminf(fmaxf(xv, 0.0f), 1.0f);
        int idx = (int)floorf(xc / hk);
        idx = min(max(idx, 0), KK - 2);
        const float tt = (xc - (float)idx * hk) / hk;
        const float t2 = tt * tt, t3 = t2 * tt;
        float4 w;
        w.x = 2.0f * t3 - 3.0f * t2 + 1.0f;       // h00
        w.y = hk * (t3 - 2.0f * t2 + tt);          // h*h10
        w.z = -2.0f * t3 + 3.0f * t2;              // h01
        w.w = hk * (t3 - t2);                      // h*h11
        if (xv < 0.0f)      { idx = 0;      w = make_float4(1.0f, xv, 0.0f, 0.0f); }
        else if (xv > 1.0f) { idx = KK - 2; w = make_float4(0.0f, 0.0f, 1.0f, xv - 1.0f); }
        s_idx[r][o] = idx;
        s_w[r][o]   = w;
    }
    __syncthreads();

    float acc[BT];
    #pragma unroll
    for (int r = 0; r < BT; r++) acc[r] = 0.0f;

    #pragma unroll 2
    for (int i = 0; i < D_IN; i++) {
        #pragma unroll
        for (int r = 0; r < BT; r++) {
            const int    idx = s_idx[r][i];
            const float4 w   = s_w[r][i];
            const float* base = g_CD + (size_t)((i * KK + idx) << 8); // *256 floats
            if (w.x != 0.0f || w.y != 0.0f)
                acc[r] += w.x * __ldg(base + o) + w.y * __ldg(base + D_OUT + o);
            if (w.z != 0.0f || w.w != 0.0f)
                acc[r] += w.z * __ldg(base + 2 * D_OUT + o) + w.w * __ldg(base + 3 * D_OUT + o);
        }
    }

    const float bv = bias[o];
    #pragma unroll
    for (int r = 0; r < BT; r++)
        out[(b0 + r) * D_OUT + o] = acc[r] + bv;
}

// ---------------------------------------------------------------------------
extern "C" void kernel_launch(void* const* d_in, const int* in_sizes, int n_in,
                              void* d_out, int out_size) {
    const float* x      = (const float*)d_in[0];   // [B, 128]
    const float* coeffs = (const float*)d_in[1];   // [128, 128, 64]
    const float* bias   = (const float*)d_in[2];   // [128]
    // d_in[3] = knots: uniform linspace(0,1,64) -> constants baked in.

    const int B = in_sizes[0] / D_IN;              // 4096

    slopes_kernel<<<(D_OUT * D_IN) / 8, 256>>>(coeffs);
    transpose_kernel<<<dim3(D_IN, D_OUT / 32), 256>>>(coeffs);
    kan_main<<<B / BT, 128>>>(x, bias, (float*)d_out, B);
}

// round 10
// speedup vs baseline: 1.0007x; 1.0007x over previous
#include <cuda_runtime.h>
#include <cuda_bf16.h>
#include <math.h>

#define D_IN   128
#define D_OUT  128
#define KK     64
#define IC     16                 // i-rows per chunk
#define NCHUNK (D_IN / IC)        // 8 partial buffers
#define BC     128                // batch rows per block
#define BMAX   4096

// Scratch (__device__ globals per allocation-free rule)
__device__ float g_C [D_IN * KK * D_OUT];            // values, [i][k][o]  (4MB)
__device__ float g_Dt[D_IN * KK * D_OUT];            // slopes, [i][k][o]  (4MB)
__device__ float g_part[NCHUNK * BMAX * D_OUT];      // partial sums       (16MB)

// ---------------------------------------------------------------------------
// Prep: fused PCHIP slopes + transpose. Block = (i, 32-wide o-tile).
// Reads coeffs[o][i][k], writes g_C/g_Dt[i][k][o] coalesced.
// ---------------------------------------------------------------------------
__global__ void __launch_bounds__(256) prep_kernel(const float* __restrict__ coeffs) {
    __shared__ float sy[32][KK];   // y values
    __shared__ float sd[32][KK];   // deltas (0..62 used)
    __shared__ float sm[32][KK];   // slopes
    const int i  = blockIdx.x;
    const int o0 = blockIdx.y * 32;
    const int t  = threadIdx.x;
    const float hk   = 1.0f / 63.0f;
    const float EPSf = 1e-12f;

    // Load 32 rows of 64 coeffs (8 floats per thread, 16B-aligned)
    {
        const int ol = t >> 3;
        const int k0 = (t & 7) * 8;
        const float* src = coeffs + ((size_t)(o0 + ol) * D_IN + i) * KK + k0;
        float4 a = *reinterpret_cast<const float4*>(src);
        float4 b = *reinterpret_cast<const float4*>(src + 4);
        sy[ol][k0 + 0] = a.x; sy[ol][k0 + 1] = a.y; sy[ol][k0 + 2] = a.z; sy[ol][k0 + 3] = a.w;
        sy[ol][k0 + 4] = b.x; sy[ol][k0 + 5] = b.y; sy[ol][k0 + 6] = b.z; sy[ol][k0 + 7] = b.w;
    }
    __syncthreads();

    // Deltas k = 0..62
    {
        const int ol = t >> 3;
        for (int k = (t & 7); k < KK - 1; k += 8)
            sd[ol][k] = (sy[ol][k + 1] - sy[ol][k]) / (hk + EPSf);
    }
    __syncthreads();

    // Slopes (reference _pchip_slopes numerics, uniform knots: w1 = w2 = 3h)
    {
        const int ol = t >> 3;
        for (int k = (t & 7); k < KK; k += 8) {
            float dk;
            if (k == 0) {
                float de = sd[ol][0];
                float di = (3.0f * hk * sd[ol][0] - hk * sd[ol][1]) / (2.0f * hk + EPSf);
                if (di * de <= 0.0f) di = 0.0f;
                if (fabsf(di) > 3.0f * fabsf(de)) di = 3.0f * de;
                dk = di;
            } else if (k == KK - 1) {
                float de = sd[ol][62];
                float di = (3.0f * hk * sd[ol][62] - hk * sd[ol][61]) / (2.0f * hk + EPSf);
                if (di * de <= 0.0f) di = 0.0f;
                if (fabsf(di) > 3.0f * fabsf(de)) di = 3.0f * de;
                dk = di;
            } else {
                float d0 = sd[ol][k - 1], d1 = sd[ol][k];
                dk = 0.0f;
                if (d0 * d1 > 0.0f) {
                    float w1 = 3.0f * hk, w2 = 3.0f * hk;
                    float denom = w1 / (d0 + EPSf) + w2 / (d1 + EPSf);
                    dk = (w1 + w2) / (denom + EPSf);
                }
            }
            sm[ol][k] = dk;
        }
    }
    __syncthreads();

    // Transposed write: 32 consecutive o per (i,k) row -> 128B coalesced
    {
        const int ol = t & 31;
        const int kb = t >> 5;           // 0..7
        #pragma unroll
        for (int kk = 0; kk < 8; kk++) {
            const int k = kb * 8 + kk;
            const size_t off = ((size_t)i * KK + k) * D_OUT + o0 + ol;
            g_C [off] = sy[ol][k];
            g_Dt[off] = sm[ol][k];
        }
    }
}

// ---------------------------------------------------------------------------
// Main eval: block = (b-chunk of 128, i-chunk of 16). 512 threads = 4 groups
// of 128 o-threads; group g accumulates 32 batch rows in registers.
// Per i: stage full 64KB {ct,dt} slice in SMEM + per-b weights, then gather
// from SMEM (broadcast idx/weights, conflict-free data reads).
// Extrapolated samples (x<0 / x>1, ~66%) read ONE row (w.z=w.w=0 skip).
// ---------------------------------------------------------------------------
__global__ void __launch_bounds__(512, 2) kan_eval(const float* __restrict__ x, int B) {
    extern __shared__ char smraw[];
    float*  s_ct  = reinterpret_cast<float*>(smraw);          // [64][128]
    float*  s_dt  = s_ct + KK * D_OUT;                        // [64][128]
    float*  s_x   = s_dt + KK * D_OUT;                        // [IC][BC]
    int*    s_idx = reinterpret_cast<int*>(s_x + IC * BC);    // [BC]
    float4* s_w   = reinterpret_cast<float4*>(s_idx + BC);    // [BC]

    const int t  = threadIdx.x;
    const int o  = t & 127;
    const int g  = t >> 7;                  // 0..3
    const int b0 = blockIdx.x * BC;
    const int i0 = blockIdx.y * IC;
    const int blbase = g << 5;
    const float hk = 1.0f / 63.0f;

    // Preload x tile [BC][IC] stored as s_x[ic][bl] (conflict-free weight reads)
    {
        const int bl  = t >> 2;
        const int icq = (t & 3) * 4;
        const int b   = b0 + bl;
        float4 v = make_float4(0.f, 0.f, 0.f, 0.f);
        if (b < B) v = *reinterpret_cast<const float4*>(x + (size_t)b * D_IN + i0 + icq);
        s_x[(icq + 0) * BC + bl] = v.x;
        s_x[(icq + 1) * BC + bl] = v.y;
        s_x[(icq + 2) * BC + bl] = v.z;
        s_x[(icq + 3) * BC + bl] = v.w;
    }

    float acc[32];
    #pragma unroll
    for (int r = 0; r < 32; r++) acc[r] = 0.0f;

    for (int ic = 0; ic < IC; ic++) {
        const int i = i0 + ic;
        __syncthreads();   // protect smem from previous iteration (and x-tile on ic=0)

        // Stage 64KB table slice (2048+2048 float4 loads, fully coalesced)
        {
            const float4* gc = reinterpret_cast<const float4*>(g_C  + (size_t)i * KK * D_OUT);
            const float4* gd = reinterpret_cast<const float4*>(g_Dt + (size_t)i * KK * D_OUT);
            float4* sc = reinterpret_cast<float4*>(s_ct);
            float4* sd = reinterpret_cast<float4*>(s_dt);
            #pragma unroll
            for (int j = 0; j < 4; j++) {
                sc[t + j * 512] = gc[t + j * 512];
                sd[t + j * 512] = gd[t + j * 512];
            }
        }

        // Per-b weights (threads 0..127; thread t = batch row t)
        if (t < BC) {
            const float xv = s_x[ic * BC + t];
            float xc = fminf(fmaxf(xv, 0.0f), 1.0f);
            int idx = (int)floorf(xc / hk);
            idx = min(max(idx, 0), KK - 2);
            const float tt = (xc - (float)idx * hk) / hk;
            const float t2 = tt * tt, t3 = t2 * tt;
            float4 w;
            w.x = 2.0f * t3 - 3.0f * t2 + 1.0f;     // h00
            w.y = hk * (t3 - 2.0f * t2 + tt);        // h*h10
            w.z = -2.0f * t3 + 3.0f * t2;            // h01
            w.w = hk * (t3 - t2);                    // h*h11
            if (xv < 0.0f)      { idx = 0;      w = make_float4(1.0f, xv,        0.0f, 0.0f); }
            else if (xv > 1.0f) { idx = KK - 1; w = make_float4(1.0f, xv - 1.0f, 0.0f, 0.0f); }
            s_idx[t] = idx;
            s_w[t]   = w;
        }
        __syncthreads();

        // Evaluate 32 batch rows for this i (idx/w broadcast; data stride-1)
        #pragma unroll
        for (int bb = 0; bb < 32; bb++) {
            const int    bl  = blbase + bb;
            const int    idx = s_idx[bl];
            const float4 w   = s_w[bl];
            const float* cp  = s_ct + (idx << 7) + o;
            const float* dp  = s_dt + (idx << 7) + o;
            float v = w.x * cp[0] + w.y * dp[0];
            if (w.z != 0.0f || w.w != 0.0f)          // warp-uniform
                v += w.z * cp[D_OUT] + w.w * dp[D_OUT];
            acc[bb] += v;
        }
    }

    // Write partials (coalesced over o)
    {
        #pragma unroll
        for (int bb = 0; bb < 32; bb++) {
            const int b = b0 + blbase + bb;
            if (b < B)
                g_part[((size_t)blockIdx.y * B + b) * D_OUT + o] = acc[bb];
        }
    }
}

// ---------------------------------------------------------------------------
// Reduce 8 partial buffers + bias -> out. float4-vectorized.
// ---------------------------------------------------------------------------
__global__ void __launch_bounds__(256) reduce_kernel(const float* __restrict__ bias,
                                                     float* __restrict__ out, int B) {
    const int idx = blockIdx.x * 256 + threadIdx.x;   // float4 index
    const int n4  = B * (D_OUT / 4);
    if (idx >= n4) return;
    const float4* p = reinterpret_cast<const float4*>(g_part);
    const size_t stride = (size_t)B * (D_OUT / 4);
    float4 s = make_float4(0.f, 0.f, 0.f, 0.f);
    #pragma unroll
    for (int c = 0; c < NCHUNK; c++) {
        float4 v = p[(size_t)c * stride + idx];
        s.x += v.x; s.y += v.y; s.z += v.z; s.w += v.w;
    }
    const float4 bv = reinterpret_cast<const float4*>(bias)[idx & (D_OUT / 4 - 1)];
    s.x += bv.x; s.y += bv.y; s.z += bv.z; s.w += bv.w;
    reinterpret_cast<float4*>(out)[idx] = s;
}

// ---------------------------------------------------------------------------
extern "C" void kernel_launch(void* const* d_in, const int* in_sizes, int n_in,
                              void* d_out, int out_size) {
    const float* x      = (const float*)d_in[0];   // [B, 128]
    const float* coeffs = (const float*)d_in[1];   // [128, 128, 64]
    const float* bias   = (const float*)d_in[2];   // [128]
    // d_in[3] = knots: uniform linspace(0,1,64) -> baked-in constants.

    const int B = in_sizes[0] / D_IN;              // 4096

    const int SMEM_BYTES = (KK * D_OUT * 2 + IC * BC) * 4 + BC * 4 + BC * 16; // 76288
    cudaFuncSetAttribute(kan_eval, cudaFuncAttributeMaxDynamicSharedMemorySize, SMEM_BYTES);

    prep_kernel<<<dim3(D_IN, D_OUT / 32), 256>>>(coeffs);
    kan_eval<<<dim3((B + BC - 1) / BC, NCHUNK), 512, SMEM_BYTES>>>(x, B);
    reduce_kernel<<<(B * (D_OUT / 4) + 255) / 256, 256>>>(bias, (float*)d_out, B);
}